// round 12
// baseline (speedup 1.0000x reference)
#include <cuda_runtime.h>
#include <cstdint>

// IDWT_2D: x [B=4, 4*C=256, H=256, W=256] f32, filters [4,2,2] f32
// s[b,g,h,w] = sum_n x[b, n*64+g, h, w]
// y[b, g*4+j, 2h+a, 2w+c] = s[b,g,h,w] * f[j,a,c]
// Output: [4, 256, 512, 512] f32
//
// FINAL (session best: 199.0us harness / 195.2us kernel, rel_err 0):
//  - One warp = one (b, g, h, half) = 128 consecutive input pixels.
//  - Thread k loads input pixels 4k..4k+3 (one LDG.128 per sub-band; 4 loads,
//    each a warp-contiguous 512B span) and writes output pixels 8k..8k+7 per
//    output row via st.global.v8.f32 (8 stores, each a warp-contiguous 1KB
//    full-sector block).
//  - 128-thread CTAs @ 16/SM, 32 regs -> 64-warp ceiling, occ ~89%.
// Moves the theoretical-minimum 1.29 GB at ~6.55 TB/s (82% of spec) — at the
// B300 mixed 1:4 R/W DRAM-controller wall. Probed and excluded as levers:
// cache hints (R2), per-warp MLP (R4), occupancy 60->92% (R5/R7/R10),
// SW pipelining (R6, regression), CTA granularity (R7/R10).

static constexpr int C = 64;                 // groups
static constexpr int H = 256;
static constexpr int W = 256;
static constexpr int SUBBAND_STRIDE = C * H * W;      // offset between sub-bands n
static constexpr int OUT_W = 2 * W;                   // 512
static constexpr int OUT_CH_STRIDE = (2 * H) * OUT_W; // 512*512

__device__ __forceinline__ void stg256(float* p,
                                       float a0, float a1, float a2, float a3,
                                       float a4, float a5, float a6, float a7) {
    asm volatile("st.global.v8.f32 [%0], {%1,%2,%3,%4,%5,%6,%7,%8};"
                 :: "l"(p), "f"(a0), "f"(a1), "f"(a2), "f"(a3),
                    "f"(a4), "f"(a5), "f"(a6), "f"(a7)
                 : "memory");
}

__global__ __launch_bounds__(128, 16) void idwt2d_kernel(
    const float* __restrict__ x,
    const float* __restrict__ filters,
    float* __restrict__ out)
{
    unsigned seg = blockIdx.x * 4u + (threadIdx.x >> 5);  // global warp id
    int lane = threadIdx.x & 31;
    int half = seg & 1;                 // which half of the input row
    int h    = (seg >> 1) & (H - 1);
    int g    = (seg >> 9) & (C - 1);
    int b    = seg >> 15;

    // thread k loads input pixels 4k..4k+3 of this half-row, per sub-band
    const float* xb = x + (((size_t)(b * 4 * C + g) * H + h) * W)
                        + half * 128 + 4 * lane;

    float4 s = *reinterpret_cast<const float4*>(xb);
    #pragma unroll
    for (int n = 1; n < 4; ++n) {
        float4 t = *reinterpret_cast<const float4*>(xb + n * SUBBAND_STRIDE);
        s.x += t.x; s.y += t.y; s.z += t.z; s.w += t.w;
    }

    // filters: [4,2,2] -> one float4 per j: {a0c0, a0c1, a1c0, a1c1}
    const float4* f4 = reinterpret_cast<const float4*>(filters);

    // output base: channel g*4, row 2h, column 256*half + 8*lane
    float* obase = out + ((size_t)(b * 4 * C + g * 4) * (2 * H) + 2 * h) * OUT_W
                       + half * 256 + 8 * lane;

    #pragma unroll
    for (int j = 0; j < 4; ++j) {
        float4 F = __ldg(f4 + j);
        float* orow = obase + (size_t)j * OUT_CH_STRIDE;

        // a = 0 row: pixels 8k..8k+7 = {s.x,s.y,s.z,s.w} x {F.x,F.y}
        stg256(orow,
               s.x * F.x, s.x * F.y, s.y * F.x, s.y * F.y,
               s.z * F.x, s.z * F.y, s.w * F.x, s.w * F.y);
        // a = 1 row: x {F.z,F.w}
        stg256(orow + OUT_W,
               s.x * F.z, s.x * F.w, s.y * F.z, s.y * F.w,
               s.z * F.z, s.z * F.w, s.w * F.z, s.w * F.w);
    }
}

extern "C" void kernel_launch(void* const* d_in, const int* in_sizes, int n_in,
                              void* d_out, int out_size) {
    const float* x       = (const float*)d_in[0];
    const float* filters = (const float*)d_in[1];
    float* out           = (float*)d_out;

    // total warps = B*C*H*2 = 131072 ; 4 warps/block -> 32768 blocks
    idwt2d_kernel<<<32768, 128>>>(x, filters, out);
}

// round 13
// speedup vs baseline: 1.0026x; 1.0026x over previous
#include <cuda_runtime.h>
#include <cstdint>

// IDWT_2D: x [B=4, 4*C=256, H=256, W=256] f32, filters [4,2,2] f32
// s[b,g,h,w] = sum_n x[b, n*64+g, h, w]
// y[b, g*4+j, 2h+a, 2w+c] = s[b,g,h,w] * f[j,a,c]
// Output: [4, 256, 512, 512] f32
//
// FINAL (session best: 199.0us harness / 195.2us kernel, rel_err 0):
//  - One warp = one (b, g, h, half) = 128 consecutive input pixels.
//  - Thread k loads input pixels 4k..4k+3 (one LDG.128 per sub-band; 4 loads,
//    each a warp-contiguous 512B span) and writes output pixels 8k..8k+7 per
//    output row via st.global.v8.f32 (8 stores, each a warp-contiguous 1KB
//    full-sector block).
//  - 128-thread CTAs @ 16/SM, 32 regs -> 64-warp ceiling, occ ~89%.
// Moves the theoretical-minimum 1.29 GB at ~6.55 TB/s (82% of spec) — at the
// B300 mixed 1:4 R/W DRAM-controller wall. Probed and excluded as levers:
// cache hints (R2), per-warp MLP (R4), occupancy 60->92% (R5/R7/R10),
// SW pipelining (R6, regression), store width (R9), CTA granularity (R7/R10).

static constexpr int C = 64;                 // groups
static constexpr int H = 256;
static constexpr int W = 256;
static constexpr int SUBBAND_STRIDE = C * H * W;      // offset between sub-bands n
static constexpr int OUT_W = 2 * W;                   // 512
static constexpr int OUT_CH_STRIDE = (2 * H) * OUT_W; // 512*512

__device__ __forceinline__ void stg256(float* p,
                                       float a0, float a1, float a2, float a3,
                                       float a4, float a5, float a6, float a7) {
    asm volatile("st.global.v8.f32 [%0], {%1,%2,%3,%4,%5,%6,%7,%8};"
                 :: "l"(p), "f"(a0), "f"(a1), "f"(a2), "f"(a3),
                    "f"(a4), "f"(a5), "f"(a6), "f"(a7)
                 : "memory");
}

__global__ __launch_bounds__(128, 16) void idwt2d_kernel(
    const float* __restrict__ x,
    const float* __restrict__ filters,
    float* __restrict__ out)
{
    unsigned seg = blockIdx.x * 4u + (threadIdx.x >> 5);  // global warp id
    int lane = threadIdx.x & 31;
    int half = seg & 1;                 // which half of the input row
    int h    = (seg >> 1) & (H - 1);
    int g    = (seg >> 9) & (C - 1);
    int b    = seg >> 15;

    // thread k loads input pixels 4k..4k+3 of this half-row, per sub-band
    const float* xb = x + (((size_t)(b * 4 * C + g) * H + h) * W)
                        + half * 128 + 4 * lane;

    float4 s = *reinterpret_cast<const float4*>(xb);
    #pragma unroll
    for (int n = 1; n < 4; ++n) {
        float4 t = *reinterpret_cast<const float4*>(xb + n * SUBBAND_STRIDE);
        s.x += t.x; s.y += t.y; s.z += t.z; s.w += t.w;
    }

    // filters: [4,2,2] -> one float4 per j: {a0c0, a0c1, a1c0, a1c1}
    const float4* f4 = reinterpret_cast<const float4*>(filters);

    // output base: channel g*4, row 2h, column 256*half + 8*lane
    float* obase = out + ((size_t)(b * 4 * C + g * 4) * (2 * H) + 2 * h) * OUT_W
                       + half * 256 + 8 * lane;

    #pragma unroll
    for (int j = 0; j < 4; ++j) {
        float4 F = __ldg(f4 + j);
        float* orow = obase + (size_t)j * OUT_CH_STRIDE;

        // a = 0 row: pixels 8k..8k+7 = {s.x,s.y,s.z,s.w} x {F.x,F.y}
        stg256(orow,
               s.x * F.x, s.x * F.y, s.y * F.x, s.y * F.y,
               s.z * F.x, s.z * F.y, s.w * F.x, s.w * F.y);
        // a = 1 row: x {F.z,F.w}
        stg256(orow + OUT_W,
               s.x * F.z, s.x * F.w, s.y * F.z, s.y * F.w,
               s.z * F.z, s.z * F.w, s.w * F.z, s.w * F.w);
    }
}

extern "C" void kernel_launch(void* const* d_in, const int* in_sizes, int n_in,
                              void* d_out, int out_size) {
    const float* x       = (const float*)d_in[0];
    const float* filters = (const float*)d_in[1];
    float* out           = (float*)d_out;

    // total warps = B*C*H*2 = 131072 ; 4 warps/block -> 32768 blocks
    idwt2d_kernel<<<32768, 128>>>(x, filters, out);
}

// round 14
// speedup vs baseline: 1.0039x; 1.0013x over previous
#include <cuda_runtime.h>
#include <cstdint>

// IDWT_2D: x [B=4, 4*C=256, H=256, W=256] f32, filters [4,2,2] f32
// s[b,g,h,w] = sum_n x[b, n*64+g, h, w]
// y[b, g*4+j, 2h+a, 2w+c] = s[b,g,h,w] * f[j,a,c]
// Output: [4, 256, 512, 512] f32
//
// FINAL (session best: 199.0us harness / 194.7us kernel, rel_err 0):
//  - One warp = one (b, g, h, half) = 128 consecutive input pixels.
//  - Thread k loads input pixels 4k..4k+3 (one LDG.128 per sub-band; 4 loads,
//    each a warp-contiguous 512B span) and writes output pixels 8k..8k+7 per
//    output row via st.global.v8.f32 (8 stores, each a warp-contiguous 1KB
//    full-sector block).
//  - 128-thread CTAs @ 16/SM, 32 regs -> 64-warp ceiling, occ ~89%.
// Moves the theoretical-minimum 1.28 GB at ~6.58 TB/s (82-83% of spec) — at
// the B300 mixed 1:4 R/W DRAM-controller wall. Probed and excluded as levers:
// cache hints (R2), per-warp MLP (R4), occupancy 60->92% (R5/R7/R10),
// SW pipelining (R6, regression), store width (R9), CTA granularity (R7/R10).

static constexpr int C = 64;                 // groups
static constexpr int H = 256;
static constexpr int W = 256;
static constexpr int SUBBAND_STRIDE = C * H * W;      // offset between sub-bands n
static constexpr int OUT_W = 2 * W;                   // 512
static constexpr int OUT_CH_STRIDE = (2 * H) * OUT_W; // 512*512

__device__ __forceinline__ void stg256(float* p,
                                       float a0, float a1, float a2, float a3,
                                       float a4, float a5, float a6, float a7) {
    asm volatile("st.global.v8.f32 [%0], {%1,%2,%3,%4,%5,%6,%7,%8};"
                 :: "l"(p), "f"(a0), "f"(a1), "f"(a2), "f"(a3),
                    "f"(a4), "f"(a5), "f"(a6), "f"(a7)
                 : "memory");
}

__global__ __launch_bounds__(128, 16) void idwt2d_kernel(
    const float* __restrict__ x,
    const float* __restrict__ filters,
    float* __restrict__ out)
{
    unsigned seg = blockIdx.x * 4u + (threadIdx.x >> 5);  // global warp id
    int lane = threadIdx.x & 31;
    int half = seg & 1;                 // which half of the input row
    int h    = (seg >> 1) & (H - 1);
    int g    = (seg >> 9) & (C - 1);
    int b    = seg >> 15;

    // thread k loads input pixels 4k..4k+3 of this half-row, per sub-band
    const float* xb = x + (((size_t)(b * 4 * C + g) * H + h) * W)
                        + half * 128 + 4 * lane;

    float4 s = *reinterpret_cast<const float4*>(xb);
    #pragma unroll
    for (int n = 1; n < 4; ++n) {
        float4 t = *reinterpret_cast<const float4*>(xb + n * SUBBAND_STRIDE);
        s.x += t.x; s.y += t.y; s.z += t.z; s.w += t.w;
    }

    // filters: [4,2,2] -> one float4 per j: {a0c0, a0c1, a1c0, a1c1}
    const float4* f4 = reinterpret_cast<const float4*>(filters);

    // output base: channel g*4, row 2h, column 256*half + 8*lane
    float* obase = out + ((size_t)(b * 4 * C + g * 4) * (2 * H) + 2 * h) * OUT_W
                       + half * 256 + 8 * lane;

    #pragma unroll
    for (int j = 0; j < 4; ++j) {
        float4 F = __ldg(f4 + j);
        float* orow = obase + (size_t)j * OUT_CH_STRIDE;

        // a = 0 row: pixels 8k..8k+7 = {s.x,s.y,s.z,s.w} x {F.x,F.y}
        stg256(orow,
               s.x * F.x, s.x * F.y, s.y * F.x, s.y * F.y,
               s.z * F.x, s.z * F.y, s.w * F.x, s.w * F.y);
        // a = 1 row: x {F.z,F.w}
        stg256(orow + OUT_W,
               s.x * F.z, s.x * F.w, s.y * F.z, s.y * F.w,
               s.z * F.z, s.z * F.w, s.w * F.z, s.w * F.w);
    }
}

extern "C" void kernel_launch(void* const* d_in, const int* in_sizes, int n_in,
                              void* d_out, int out_size) {
    const float* x       = (const float*)d_in[0];
    const float* filters = (const float*)d_in[1];
    float* out           = (float*)d_out;

    // total warps = B*C*H*2 = 131072 ; 4 warps/block -> 32768 blocks
    idwt2d_kernel<<<32768, 128>>>(x, filters, out);
}